// round 4
// baseline (speedup 1.0000x reference)
#include <cuda_runtime.h>
#include <cuda_bf16.h>

// One-hot: x [8,1024] int32 -> out [8,1024,32000] fp32 (1.048 GB of stores).
// Fused, half-row blocks to shrink wave-tail quantization:
//   grid = 16384 blocks (2 per row), 256 threads, 4000 float4 per block
//   = 15 full iters + 160-thread tail. 8 blocks/SM -> 100% occupancy cap,
//   ~13.8 waves -> tail cost halves vs the 320-thread full-row version.
// The 1.0f overwrite is done by the same thread that zeroed that slot
// (owner tid == o & 255), so same-thread same-address ordering applies.

static constexpr int NUM_CLASS = 32000;
static constexpr int NC4       = NUM_CLASS / 4;   // 8000 float4 per row
static constexpr int ROWS      = 8 * 1024;        // 8192
static constexpr int HALF      = NC4 / 2;         // 4000 float4 per block
static constexpr int THREADS   = 256;
static constexpr int FULL_IT   = HALF / THREADS;  // 15
static constexpr int TAIL      = HALF - FULL_IT * THREADS;  // 160

__global__ void __launch_bounds__(THREADS)
onehot_halfrow_kernel(const int* __restrict__ x, float4* __restrict__ out)
{
    const int row  = blockIdx.x >> 1;
    const int half = blockIdx.x & 1;
    const int tid  = threadIdx.x;

    const int t = __ldg(x + row);                 // issued early, stores don't wait

    float4* p = out + (long long)row * NC4 + half * HALF;
    const float4 z = make_float4(0.f, 0.f, 0.f, 0.f);

#pragma unroll
    for (int i = 0; i < FULL_IT; ++i) {
        __stcs(p + i * THREADS + tid, z);         // evict-first streaming store
    }
    if (tid < TAIL) {
        __stcs(p + FULL_IT * THREADS + tid, z);
    }

    // one-hot overwrite: offset of the hot float4 within this half-row
    const int o = (t >> 2) - half * HALF;
    if (o >= 0 && o < HALF && (o & (THREADS - 1)) == tid) {
        reinterpret_cast<float*>(p + o)[t & 3] = 1.0f;  // same thread zeroed p[o]
    }
}

extern "C" void kernel_launch(void* const* d_in, const int* in_sizes, int n_in,
                              void* d_out, int out_size)
{
    const int* x = (const int*)d_in[0];
    onehot_halfrow_kernel<<<ROWS * 2, THREADS>>>(x, (float4*)d_out);
}